// round 3
// baseline (speedup 1.0000x reference)
#include <cuda_runtime.h>
#include <cuda_bf16.h>
#include <cstdint>

#define NN   12288
#define KK   32
#define DD   128

// Scratch: G = raw_features @ W_lin^T   (N x 128 fp32, 6.3 MB)
__device__ __align__(16) float g_G[NN * DD];

// ---------------------------------------------------------------------------
// packed f32x2 helpers (sm_103a: FFMA2 only reachable via PTX fma.rn.f32x2)
// ---------------------------------------------------------------------------
__device__ __forceinline__ unsigned long long pack_dup(float x) {
    unsigned long long r;
    asm("mov.b64 %0, {%1, %1};" : "=l"(r) : "f"(x));
    return r;
}
__device__ __forceinline__ void fma2(unsigned long long& d,
                                     unsigned long long a,
                                     unsigned long long b) {
    asm("fma.rn.f32x2 %0, %1, %2, %0;" : "+l"(d) : "l"(a), "l"(b));
}

// ---------------------------------------------------------------------------
// Kernel 1: G[m][n] = sum_k F[m][k] * W[n][k]
// 192 blocks x 256 threads, 64x128 tile, FFMA2 microtile 8 rows x 2 col-pairs.
//   Fs: 64 x (pad 129)  — a-reads are warp-broadcast (ty uniform per warp)
//   Wt: transposed W, k-major rows of 128 cols, pad 130 (even => LDS.64 aligned;
//       staging banks (2k+n)%32 => worst 2-way; inner reads contiguous 256B)
// ---------------------------------------------------------------------------
__global__ void __launch_bounds__(256, 2)
gemm_G_kernel(const float* __restrict__ F, const float* __restrict__ W)
{
    extern __shared__ float sm[];
    float* Fs = sm;                 // 64 * 129
    float* Wt = sm + 64 * 129;      // 128 * 130  (Wt[k*130 + n] = W[n][k])

    const int tid = threadIdx.x;
    const int bm  = blockIdx.x;
    const float* Fblk = F + (size_t)bm * 64 * DD;

    // Stage F tile (coalesced, stride-1 => conflict-free)
    #pragma unroll 4
    for (int idx = tid; idx < 64 * 128; idx += 256) {
        int r = idx >> 7, c = idx & 127;
        Fs[r * 129 + c] = Fblk[idx];
    }
    // Stage W transposed
    #pragma unroll 8
    for (int idx = tid; idx < 128 * 128; idx += 256) {
        int n = idx >> 7, k = idx & 127;
        Wt[k * 130 + n] = W[idx];
    }
    __syncthreads();

    const int tx = tid & 31;   // pair-column slot (cols 2*(tx+32j))
    const int ty = tid >> 5;   // row slot (rows ty + 8i), uniform per warp

    unsigned long long acc[8][2];
    #pragma unroll
    for (int i = 0; i < 8; i++) { acc[i][0] = 0ULL; acc[i][1] = 0ULL; }

    #pragma unroll 4
    for (int kk = 0; kk < 128; kk++) {
        unsigned long long b2[2];
        #pragma unroll
        for (int j = 0; j < 2; j++)
            b2[j] = *reinterpret_cast<const unsigned long long*>(
                        &Wt[kk * 130 + 2 * (tx + 32 * j)]);
        #pragma unroll
        for (int i = 0; i < 8; i++) {
            unsigned long long a2 = pack_dup(Fs[(ty + 8 * i) * 129 + kk]);
            fma2(acc[i][0], a2, b2[0]);
            fma2(acc[i][1], a2, b2[1]);
        }
    }

    float* Gout = g_G + (size_t)bm * 64 * DD;
    #pragma unroll
    for (int i = 0; i < 8; i++) {
        int m = ty + 8 * i;
        #pragma unroll
        for (int j = 0; j < 2; j++) {
            int n = 2 * (tx + 32 * j);
            *reinterpret_cast<unsigned long long*>(&Gout[m * DD + n]) = acc[i][j];
        }
    }
}

// ---------------------------------------------------------------------------
// Kernel 2: out[b][d] = relu( sum_k w[b][k] * G[nb[b][k]][d] + bias[d] )
// One warp per node; lane l owns columns 4l..4l+3 (float4).
// (nb, w) live in registers (lane k holds k-th pair), broadcast via shfl.
// ---------------------------------------------------------------------------
__global__ void __launch_bounds__(256)
gather_kernel(const int* __restrict__ nodes,
              const int* __restrict__ neighbors,
              const float* __restrict__ rew,
              const float* __restrict__ b_lin,
              float* __restrict__ out)
{
    const int lane = threadIdx.x & 31;
    const int wrp  = threadIdx.x >> 5;
    const int b    = blockIdx.x * 8 + wrp;

    const int node = nodes[b];                       // broadcast load
    const int nb_l = neighbors[b * KK + lane];       // coalesced
    float w_l = 0.0f;
    if (nb_l != node)
        w_l = __ldg(&rew[(size_t)node * NN + nb_l]); // scattered 32B sectors

    float4 acc = make_float4(0.f, 0.f, 0.f, 0.f);

    #pragma unroll
    for (int k = 0; k < KK; k++) {
        const int   nbk = __shfl_sync(0xffffffffu, nb_l, k);
        const float wk  = __shfl_sync(0xffffffffu, w_l,  k);
        const float4 g = __ldg(reinterpret_cast<const float4*>(
                                   &g_G[(size_t)nbk * DD + lane * 4]));
        acc.x = fmaf(wk, g.x, acc.x);
        acc.y = fmaf(wk, g.y, acc.y);
        acc.z = fmaf(wk, g.z, acc.z);
        acc.w = fmaf(wk, g.w, acc.w);
    }

    const float4 bias = __ldg(reinterpret_cast<const float4*>(&b_lin[lane * 4]));
    float4 o;
    o.x = fmaxf(acc.x + bias.x, 0.f);
    o.y = fmaxf(acc.y + bias.y, 0.f);
    o.z = fmaxf(acc.z + bias.z, 0.f);
    o.w = fmaxf(acc.w + bias.w, 0.f);
    *reinterpret_cast<float4*>(&out[(size_t)b * DD + lane * 4]) = o;
}

// ---------------------------------------------------------------------------
// Launch. Inputs: nodes(i32 N), neighbors(i32 N*K), raw_features(f32 N*128),
//                 reweighted(f32 N*N), W_lin(f32 128*128), b_lin(f32 128)
// ---------------------------------------------------------------------------
extern "C" void kernel_launch(void* const* d_in, const int* in_sizes, int n_in,
                              void* d_out, int out_size)
{
    const int*   nodes      = (const int*)  d_in[0];
    const int*   neighbors  = (const int*)  d_in[1];
    const float* raw_feats  = (const float*)d_in[2];
    const float* reweighted = (const float*)d_in[3];
    const float* W_lin      = (const float*)d_in[4];
    const float* b_lin      = (const float*)d_in[5];
    float*       out        = (float*)d_out;

    const int smem = (64 * 129 + 128 * 130) * (int)sizeof(float);  // 99584 B
    static bool attr_set = false;
    if (!attr_set) {
        cudaFuncSetAttribute(gemm_G_kernel,
                             cudaFuncAttributeMaxDynamicSharedMemorySize, smem);
        attr_set = true;
    }

    gemm_G_kernel<<<NN / 64, 256, smem>>>(raw_feats, W_lin);
    gather_kernel<<<NN / 8, 256>>>(nodes, neighbors, reweighted, b_lin, out);
}

// round 4
// speedup vs baseline: 1.1911x; 1.1911x over previous
#include <cuda_runtime.h>
#include <cuda_bf16.h>
#include <cstdint>

#define NN   12288
#define KK   32
#define DD   128

typedef unsigned long long ull;

// Scratch: G = raw_features @ W_lin^T   (N x 128 fp32, 6.3 MB)
__device__ __align__(16) float g_G[NN * DD];

// ---------------------------------------------------------------------------
// packed f32x2 helpers (sm_103a: FFMA2 only reachable via PTX fma.rn.f32x2)
// ---------------------------------------------------------------------------
__device__ __forceinline__ ull pack_dup(float x) {
    ull r;
    asm("mov.b64 %0, {%1, %1};" : "=l"(r) : "f"(x));
    return r;
}
__device__ __forceinline__ void fma2(ull& d, ull a, ull b) {
    asm("fma.rn.f32x2 %0, %1, %2, %0;" : "+l"(d) : "l"(a), "l"(b));
}
__device__ __forceinline__ void unpack2(float& lo, float& hi, ull v) {
    asm("mov.b64 {%0, %1}, %2;" : "=f"(lo), "=f"(hi) : "l"(v));
}

// ---------------------------------------------------------------------------
// Kernel 1: G[m][n] = sum_k F[m][k] * W[n][k]
// Grid (192, 2): 64-row x 64-col tiles. 128 threads, 3 CTAs/SM -> 1 wave.
// Microtile: 8 rows x 4 cols per thread, accumulators paired over rows.
//   Fst[k][m]  (transposed F tile, pad 66): row-pairs read as LDS.64
//   Wt [k][n]  (transposed W tile, pad 66): 4 col scalars as 2x LDS.64
// Inner loop: 4 LDS.64(a) + 2 LDS.64(b) + 4 mov(dup) + 16 FFMA2 = 26 inst
// for 32 FMA-pairs (64 FMAs).
// ---------------------------------------------------------------------------
__global__ void __launch_bounds__(128, 3)
gemm_G_kernel(const float* __restrict__ F, const float* __restrict__ W)
{
    extern __shared__ float sm[];
    float* Fst = sm;                 // 128 * 66  (Fst[k*66 + m])
    float* Wt  = sm + 128 * 66;      // 128 * 66  (Wt [k*66 + n])

    const int tid = threadIdx.x;
    const int bm  = blockIdx.x;      // row tile (64 rows)
    const int bn  = blockIdx.y;      // col tile (64 cols)

    const float* Fblk = F + (size_t)bm * 64 * DD;
    const float* Wblk = W + (size_t)bn * 64 * DD;   // W[n][k] row-major

    // Stage transposed tiles (coalesced LDG; STS 2-way worst case)
    #pragma unroll 8
    for (int idx = tid; idx < 64 * 128; idx += 128) {
        int r = idx >> 7, k = idx & 127;
        Fst[k * 66 + r] = Fblk[idx];
        Wt [k * 66 + r] = Wblk[idx];
    }
    __syncthreads();

    const int tx = tid & 15;   // cols 4*tx .. 4*tx+3
    const int ty = tid >> 4;   // rows 8*ty .. 8*ty+7

    ull acc[4][4];             // [row-pair p][col c]
    #pragma unroll
    for (int p = 0; p < 4; p++)
        #pragma unroll
        for (int c = 0; c < 4; c++)
            acc[p][c] = 0ULL;

    #pragma unroll 4
    for (int kk = 0; kk < 128; kk++) {
        const float* fr = &Fst[kk * 66 + 8 * ty];
        ull a2[4];
        #pragma unroll
        for (int p = 0; p < 4; p++)
            a2[p] = *reinterpret_cast<const ull*>(&fr[2 * p]);

        float2 b01 = *reinterpret_cast<const float2*>(&Wt[kk * 66 + 4 * tx]);
        float2 b23 = *reinterpret_cast<const float2*>(&Wt[kk * 66 + 4 * tx + 2]);
        ull bd[4];
        bd[0] = pack_dup(b01.x); bd[1] = pack_dup(b01.y);
        bd[2] = pack_dup(b23.x); bd[3] = pack_dup(b23.y);

        #pragma unroll
        for (int p = 0; p < 4; p++)
            #pragma unroll
            for (int c = 0; c < 4; c++)
                fma2(acc[p][c], a2[p], bd[c]);
    }

    // Epilogue: unpack row-pairs, scalar stores (epilogue is ~3% of work)
    const int gm0 = bm * 64 + 8 * ty;
    const int gn0 = bn * 64 + 4 * tx;
    #pragma unroll
    for (int p = 0; p < 4; p++) {
        #pragma unroll
        for (int c = 0; c < 4; c++) {
            float lo, hi;
            unpack2(lo, hi, acc[p][c]);
            g_G[(size_t)(gm0 + 2 * p)     * DD + gn0 + c] = lo;
            g_G[(size_t)(gm0 + 2 * p + 1) * DD + gn0 + c] = hi;
        }
    }
}

// ---------------------------------------------------------------------------
// Kernel 2: out[b][d] = relu( sum_k w[b][k] * G[nb[b][k]][d] + bias[d] )
// 8 nodes / 256-thread block; one warp per node, lane owns 4 columns (float4).
// (nb, w) staged in smem; k-loop in chunks of 8 with batched loads (MLP=8).
// __launch_bounds__(256,3) -> ~85 regs so the 8 float4 stay in flight.
// ---------------------------------------------------------------------------
__global__ void __launch_bounds__(256, 3)
gather_kernel(const int* __restrict__ nodes,
              const int* __restrict__ neighbors,
              const float* __restrict__ rew,
              const float* __restrict__ b_lin,
              float* __restrict__ out)
{
    __shared__ int   nb_s[8][KK];
    __shared__ float w_s [8][KK];

    const int tid  = threadIdx.x;
    const int b0   = blockIdx.x * 8;

    // Stage: 256 threads == 8 nodes x 32 k exactly
    {
        const int ln = tid >> 5;
        const int k  = tid & 31;
        const int b  = b0 + ln;
        const int node = nodes[b];
        const int nb   = neighbors[b * KK + k];
        float w = 0.0f;
        if (nb != node)
            w = __ldg(&rew[(size_t)node * NN + nb]);
        nb_s[ln][k] = nb;
        w_s [ln][k] = w;
    }
    __syncthreads();

    const int ln   = tid >> 5;       // local node (warp id)
    const int lane = tid & 31;
    const int d4   = lane * 4;
    const int b    = b0 + ln;

    float4 acc = make_float4(0.f, 0.f, 0.f, 0.f);

    #pragma unroll
    for (int kb = 0; kb < KK; kb += 8) {
        float4 g[8];
        float  wv[8];
        #pragma unroll
        for (int u = 0; u < 8; u++) {
            const int nb = nb_s[ln][kb + u];
            wv[u] = w_s[ln][kb + u];
            g[u]  = __ldg(reinterpret_cast<const float4*>(
                              &g_G[(size_t)nb * DD + d4]));
        }
        #pragma unroll
        for (int u = 0; u < 8; u++) {
            acc.x = fmaf(wv[u], g[u].x, acc.x);
            acc.y = fmaf(wv[u], g[u].y, acc.y);
            acc.z = fmaf(wv[u], g[u].z, acc.z);
            acc.w = fmaf(wv[u], g[u].w, acc.w);
        }
    }

    const float4 bias = __ldg(reinterpret_cast<const float4*>(&b_lin[d4]));
    float4 o;
    o.x = fmaxf(acc.x + bias.x, 0.f);
    o.y = fmaxf(acc.y + bias.y, 0.f);
    o.z = fmaxf(acc.z + bias.z, 0.f);
    o.w = fmaxf(acc.w + bias.w, 0.f);
    *reinterpret_cast<float4*>(&out[(size_t)b * DD + d4]) = o;
}

// ---------------------------------------------------------------------------
// Launch. Inputs: nodes(i32 N), neighbors(i32 N*K), raw_features(f32 N*128),
//                 reweighted(f32 N*N), W_lin(f32 128*128), b_lin(f32 128)
// ---------------------------------------------------------------------------
extern "C" void kernel_launch(void* const* d_in, const int* in_sizes, int n_in,
                              void* d_out, int out_size)
{
    const int*   nodes      = (const int*)  d_in[0];
    const int*   neighbors  = (const int*)  d_in[1];
    const float* raw_feats  = (const float*)d_in[2];
    const float* reweighted = (const float*)d_in[3];
    const float* W_lin      = (const float*)d_in[4];
    const float* b_lin      = (const float*)d_in[5];
    float*       out        = (float*)d_out;

    const int smem = 2 * 128 * 66 * (int)sizeof(float);  // 67584 B
    static bool attr_set = false;
    if (!attr_set) {
        cudaFuncSetAttribute(gemm_G_kernel,
                             cudaFuncAttributeMaxDynamicSharedMemorySize, smem);
        attr_set = true;
    }

    dim3 ggrid(NN / 64, DD / 64);
    gemm_G_kernel<<<ggrid, 128, smem>>>(raw_feats, W_lin);
    gather_kernel<<<NN / 8, 256>>>(nodes, neighbors, reweighted, b_lin, out);
}

// round 5
// speedup vs baseline: 1.3724x; 1.1522x over previous
#include <cuda_runtime.h>
#include <cuda_fp16.h>
#include <cstdint>

#define NN   12288
#define KK   32
#define DD   128

typedef unsigned long long ull;

// Scratch: G = raw_features @ W_lin^T, stored as fp16 (N x 128, 3.15 MB)
__device__ __align__(16) __half g_Gh[NN * DD];

// ---------------------------------------------------------------------------
// packed f32x2 helpers (sm_103a FFMA2 via PTX fma.rn.f32x2)
// ---------------------------------------------------------------------------
__device__ __forceinline__ ull pack_dup(float x) {
    ull r;
    asm("mov.b64 %0, {%1, %1};" : "=l"(r) : "f"(x));
    return r;
}
__device__ __forceinline__ void fma2(ull& d, ull a, ull b) {
    asm("fma.rn.f32x2 %0, %1, %2, %0;" : "+l"(d) : "l"(a), "l"(b));
}
__device__ __forceinline__ void unpack2(float& lo, float& hi, ull v) {
    asm("mov.b64 {%0, %1}, %2;" : "=f"(lo), "=f"(hi) : "l"(v));
}

// ---------------------------------------------------------------------------
// Kernel 1: G[m][n] = sum_k F[m][k] * W[n][k], output fp16.
// Grid (192, 2): 64x64 tiles, 128 threads, 3 CTAs/SM.
// Microtile 8 rows x 4 cols, accumulators paired over rows (FFMA2).
// ---------------------------------------------------------------------------
__global__ void __launch_bounds__(128, 3)
gemm_G_kernel(const float* __restrict__ F, const float* __restrict__ W)
{
    extern __shared__ float sm[];
    float* Fst = sm;                 // 128 * 66  (Fst[k*66 + m])
    float* Wt  = sm + 128 * 66;      // 128 * 66  (Wt [k*66 + n])

    const int tid = threadIdx.x;
    const int bm  = blockIdx.x;
    const int bn  = blockIdx.y;

    const float* Fblk = F + (size_t)bm * 64 * DD;
    const float* Wblk = W + (size_t)bn * 64 * DD;

    #pragma unroll 8
    for (int idx = tid; idx < 64 * 128; idx += 128) {
        int r = idx >> 7, k = idx & 127;
        Fst[k * 66 + r] = Fblk[idx];
        Wt [k * 66 + r] = Wblk[idx];
    }
    __syncthreads();

    const int tx = tid & 15;   // cols 4*tx .. 4*tx+3
    const int ty = tid >> 4;   // rows 8*ty .. 8*ty+7

    ull acc[4][4];
    #pragma unroll
    for (int p = 0; p < 4; p++)
        #pragma unroll
        for (int c = 0; c < 4; c++)
            acc[p][c] = 0ULL;

    #pragma unroll 4
    for (int kk = 0; kk < 128; kk++) {
        const float* fr = &Fst[kk * 66 + 8 * ty];
        ull a2[4];
        #pragma unroll
        for (int p = 0; p < 4; p++)
            a2[p] = *reinterpret_cast<const ull*>(&fr[2 * p]);

        float2 b01 = *reinterpret_cast<const float2*>(&Wt[kk * 66 + 4 * tx]);
        float2 b23 = *reinterpret_cast<const float2*>(&Wt[kk * 66 + 4 * tx + 2]);
        ull bd[4];
        bd[0] = pack_dup(b01.x); bd[1] = pack_dup(b01.y);
        bd[2] = pack_dup(b23.x); bd[3] = pack_dup(b23.y);

        #pragma unroll
        for (int p = 0; p < 4; p++)
            #pragma unroll
            for (int c = 0; c < 4; c++)
                fma2(acc[p][c], a2[p], bd[c]);
    }

    // Epilogue: unpack to v[row][col], convert to half, 8B stores.
    float v[8][4];
    #pragma unroll
    for (int p = 0; p < 4; p++)
        #pragma unroll
        for (int c = 0; c < 4; c++) {
            float lo, hi;
            unpack2(lo, hi, acc[p][c]);
            v[2 * p][c]     = lo;
            v[2 * p + 1][c] = hi;
        }

    const int gm0 = bm * 64 + 8 * ty;
    const int gn0 = bn * 64 + 4 * tx;
    #pragma unroll
    for (int r = 0; r < 8; r++) {
        __half2 h01 = __floats2half2_rn(v[r][0], v[r][1]);
        __half2 h23 = __floats2half2_rn(v[r][2], v[r][3]);
        uint2 st;
        st.x = *reinterpret_cast<unsigned*>(&h01);
        st.y = *reinterpret_cast<unsigned*>(&h23);
        *reinterpret_cast<uint2*>(&g_Gh[(size_t)(gm0 + r) * DD + gn0]) = st;
    }
}

// ---------------------------------------------------------------------------
// Kernel 2: out[b][d] = relu( sum_k w[b][k] * G[nb[b][k]][d] + bias[d] )
// 8 nodes / 256-thread block; warp per node, lane owns 4 cols (half4 = uint2).
// k in chunks of 8 (MLP=8, 16 regs of payload). fp32 accumulate.
// ---------------------------------------------------------------------------
__global__ void __launch_bounds__(256)
gather_kernel(const int* __restrict__ nodes,
              const int* __restrict__ neighbors,
              const float* __restrict__ rew,
              const float* __restrict__ b_lin,
              float* __restrict__ out)
{
    __shared__ int   nb_s[8][KK];
    __shared__ float w_s [8][KK];

    const int tid = threadIdx.x;
    const int b0  = blockIdx.x * 8;

    {   // 256 threads == 8 nodes x 32 k exactly
        const int ln = tid >> 5;
        const int k  = tid & 31;
        const int b  = b0 + ln;
        const int node = nodes[b];
        const int nb   = neighbors[b * KK + k];
        float w = 0.0f;
        if (nb != node)
            w = __ldg(&rew[(size_t)node * NN + nb]);
        nb_s[ln][k] = nb;
        w_s [ln][k] = w;
    }
    __syncthreads();

    const int ln   = tid >> 5;
    const int lane = tid & 31;
    const int d4   = lane * 4;
    const int b    = b0 + ln;

    float4 acc = make_float4(0.f, 0.f, 0.f, 0.f);

    #pragma unroll
    for (int kb = 0; kb < KK; kb += 8) {
        uint2 g[8];
        float wv[8];
        #pragma unroll
        for (int u = 0; u < 8; u++) {
            const int nb = nb_s[ln][kb + u];
            wv[u] = w_s[ln][kb + u];
            g[u]  = __ldg(reinterpret_cast<const uint2*>(
                              &g_Gh[(size_t)nb * DD + d4]));
        }
        #pragma unroll
        for (int u = 0; u < 8; u++) {
            float2 lo = __half22float2(*reinterpret_cast<__half2*>(&g[u].x));
            float2 hi = __half22float2(*reinterpret_cast<__half2*>(&g[u].y));
            acc.x = fmaf(wv[u], lo.x, acc.x);
            acc.y = fmaf(wv[u], lo.y, acc.y);
            acc.z = fmaf(wv[u], hi.x, acc.z);
            acc.w = fmaf(wv[u], hi.y, acc.w);
        }
    }

    const float4 bias = __ldg(reinterpret_cast<const float4*>(&b_lin[d4]));
    float4 o;
    o.x = fmaxf(acc.x + bias.x, 0.f);
    o.y = fmaxf(acc.y + bias.y, 0.f);
    o.z = fmaxf(acc.z + bias.z, 0.f);
    o.w = fmaxf(acc.w + bias.w, 0.f);
    *reinterpret_cast<float4*>(&out[(size_t)b * DD + d4]) = o;
}

// ---------------------------------------------------------------------------
// Launch. Inputs: nodes(i32 N), neighbors(i32 N*K), raw_features(f32 N*128),
//                 reweighted(f32 N*N), W_lin(f32 128*128), b_lin(f32 128)
// ---------------------------------------------------------------------------
extern "C" void kernel_launch(void* const* d_in, const int* in_sizes, int n_in,
                              void* d_out, int out_size)
{
    const int*   nodes      = (const int*)  d_in[0];
    const int*   neighbors  = (const int*)  d_in[1];
    const float* raw_feats  = (const float*)d_in[2];
    const float* reweighted = (const float*)d_in[3];
    const float* W_lin      = (const float*)d_in[4];
    const float* b_lin      = (const float*)d_in[5];
    float*       out        = (float*)d_out;

    const int smem = 2 * 128 * 66 * (int)sizeof(float);  // 67584 B
    static bool attr_set = false;
    if (!attr_set) {
        cudaFuncSetAttribute(gemm_G_kernel,
                             cudaFuncAttributeMaxDynamicSharedMemorySize, smem);
        attr_set = true;
    }

    dim3 ggrid(NN / 64, DD / 64);
    gemm_G_kernel<<<ggrid, 128, smem>>>(raw_feats, W_lin);
    gather_kernel<<<NN / 8, 256>>>(nodes, neighbors, reweighted, b_lin, out);
}